// round 12
// baseline (speedup 1.0000x reference)
#include <cuda_runtime.h>
#include <cuda_bf16.h>
#include <stdint.h>

#define B_ 128
#define T_ 1024
#define I_ 64
#define W_ 32
#define H_ 256
#define BT_ (B_*T_)

typedef unsigned long long u64;

// ---------------- scratch (__device__ globals are allowed) ------------------
__device__ float g_e     [(size_t)BT_*H_];   // [T][B][H]
__device__ float g_pre_ho[(size_t)BT_*H_];   // [T][B][H]
__device__ float g_pre_i [(size_t)BT_*H_];
__device__ float g_pre_g [(size_t)BT_*H_];
__device__ float g_pre_f [(size_t)BT_*H_];
__device__ float g_pre_o [(size_t)BT_*H_];

__device__ __forceinline__ float sigm(float x) { return 1.f / (1.f + __expf(-x)); }
__device__ __forceinline__ float tanh_f(float x) {
    float e = __expf(2.f * x);
    return 1.f - __fdividef(2.f, e + 1.f);
}

// packed f32x2 FMA (sm_100+)
__device__ __forceinline__ u64 fma2(u64 a, u64 b, u64 c) {
    u64 d;
    asm("fma.rn.f32x2 %0, %1, %2, %3;" : "=l"(d) : "l"(a), "l"(b), "l"(c));
    return d;
}
__device__ __forceinline__ float red2(u64 v) {
    float x, y;
    asm("mov.b64 {%0, %1}, %2;" : "=f"(x), "=f"(y) : "l"(v));
    return x + y;
}

__device__ __forceinline__ uint32_t smem_u32(const void* p) {
    uint32_t a;
    asm("{ .reg .u64 t; cvta.to.shared.u64 t, %1; cvt.u32.u64 %0, t; }" : "=r"(a) : "l"(p));
    return a;
}
#define CLUSTER_SYNC() do { \
    asm volatile("barrier.cluster.arrive.aligned;" ::: "memory"); \
    asm volatile("barrier.cluster.wait.aligned;"   ::: "memory"); \
} while (0)

// remote DSMEM 8-byte store fused with tx-signal on dest CTA's mbarrier
__device__ __forceinline__ void st_async_b64(uint32_t raddr, u64 v, uint32_t rmbar) {
    asm volatile(
        "st.async.shared::cluster.mbarrier::complete_tx::bytes.b64 [%0], %1, [%2];"
        :: "r"(raddr), "l"(v), "r"(rmbar) : "memory");
}
__device__ __forceinline__ void mb_init(uint32_t mbar, uint32_t cnt) {
    asm volatile("mbarrier.init.shared.b64 [%0], %1;" :: "r"(mbar), "r"(cnt) : "memory");
}
__device__ __forceinline__ void mb_expect_tx(uint32_t mbar, uint32_t bytes) {
    asm volatile("mbarrier.arrive.expect_tx.shared.b64 _, [%0], %1;"
                 :: "r"(mbar), "r"(bytes) : "memory");
}
__device__ __forceinline__ void mb_wait(uint32_t mbar, uint32_t parity) {
    uint32_t done;
    asm volatile(
        "{\n\t.reg .pred p;\n\t"
        "mbarrier.try_wait.parity.acquire.cluster.shared::cta.b64 p, [%1], %2;\n\t"
        "selp.b32 %0, 1, 0, p;\n\t}"
        : "=r"(done) : "r"(mbar), "r"(parity) : "memory");
    if (!done) {
        asm volatile(
            "{\n\t.reg .pred P1;\n\t"
            "WL_%=:\n\t"
            "mbarrier.try_wait.parity.acquire.cluster.shared::cta.b64 P1, [%0], %1, 0x989680;\n\t"
            "@P1 bra.uni WD_%=;\n\t"
            "bra.uni WL_%=;\n\t"
            "WD_%=:\n\t}"
            :: "r"(mbar), "r"(parity) : "memory");
    }
}

// ========================== Kernel E: e = sigmoid(xw @ w_e^T + b_e) =========
__global__ void k_e(const float* __restrict__ xw, const float* __restrict__ w_e,
                    const float* __restrict__ b_e)
{
    __shared__ float sx[8][32];
    int h = threadIdx.x;
    int bt0 = blockIdx.x * 8;
    {
        int p = h >> 5, k = h & 31;
        int bt = bt0 + p;
        int b = bt >> 10, t = bt & 1023;
        sx[p][k] = xw[((size_t)b*T_ + t)*W_ + k];
    }
    __syncthreads();
    float4 wr[8];
    const float4* wp = (const float4*)(w_e + (size_t)h*W_);
#pragma unroll
    for (int u = 0; u < 8; ++u) wr[u] = wp[u];
    float bias = b_e[h];
#pragma unroll
    for (int p = 0; p < 8; ++p) {
        float acc = bias;
#pragma unroll
        for (int u = 0; u < 8; ++u) {
            acc += wr[u].x*sx[p][4*u+0] + wr[u].y*sx[p][4*u+1]
                 + wr[u].z*sx[p][4*u+2] + wr[u].w*sx[p][4*u+3];
        }
        int bt = bt0 + p;
        int b = bt >> 10, t = bt & 1023;
        g_e[((size_t)t*B_ + b)*H_ + h] = sigm(acc);
    }
}

// ------- shared helpers for 64x64 fp32x2 tiles (k-pair float2 layout) -------
__device__ __forceinline__ void stage_panel(float2* S, const float4* src,
                                            int r, int q)
{
#pragma unroll
    for (int u = 0; u < 4; ++u) {
        float4 v = src[q + 4*u];
        int k2 = 2*(q + 4*u);
        S[k2*66 + r]       = make_float2(v.x, v.y);
        S[(k2+1)*66 + r]   = make_float2(v.z, v.w);
    }
}
__device__ __forceinline__ void accum64(const float2* A2, const float2* B2,
                                        int tx, int ty, u64 acc[4][4])
{
#pragma unroll 8
    for (int k2 = 0; k2 < 32; ++k2) {
        ulonglong2 aL = *(const ulonglong2*)(A2 + k2*66 + ty*4);
        ulonglong2 aH = *(const ulonglong2*)(A2 + k2*66 + ty*4 + 2);
        ulonglong2 bL = *(const ulonglong2*)(B2 + k2*66 + tx*4);
        ulonglong2 bH = *(const ulonglong2*)(B2 + k2*66 + tx*4 + 2);
        u64 av[4] = {aL.x, aL.y, aH.x, aH.y};
        u64 bv[4] = {bL.x, bL.y, bH.x, bH.y};
#pragma unroll
        for (int i = 0; i < 4; ++i)
#pragma unroll
            for (int j = 0; j < 4; ++j) acc[i][j] = fma2(av[i], bv[j], acc[i][j]);
    }
}

// ===== Kernel XE: pre_X = x@w_Xx^T (+ e@w_Xe^T for i,f,o) + b_X  ============
__global__ void k_xe(const float* __restrict__ x,
                     const float* __restrict__ wx0, const float* __restrict__ wx1,
                     const float* __restrict__ wx2, const float* __restrict__ wx3,
                     const float* __restrict__ we0, const float* __restrict__ we1,
                     const float* __restrict__ we2,
                     const float* __restrict__ bi, const float* __restrict__ bf,
                     const float* __restrict__ bo, const float* __restrict__ bg)
{
    __shared__ float2 A2[32*66];
    __shared__ float2 B2[32*66];
    int m0 = blockIdx.x * 64;
    int gy = blockIdx.y;
    int mat = gy >> 2;
    int col0 = (gy & 3) * 64;
    const float* wx = (mat==0)?wx0:(mat==1)?wx1:(mat==2)?wx2:wx3;
    int tid = threadIdx.x;
    int r = tid >> 2, q = tid & 3;
    int tx = tid & 15, ty = tid >> 4;
    int m = m0 + r;
    int b = m & (B_-1), t = m >> 7;

    u64 acc[4][4] = {};
    stage_panel(A2, (const float4*)(x + ((size_t)b*T_ + t)*I_), r, q);
    stage_panel(B2, (const float4*)(wx + (size_t)(col0 + r)*I_), r, q);
    __syncthreads();
    accum64(A2, B2, tx, ty, acc);
    if (mat < 3) {
        const float* we = (mat==0)?we0:(mat==1)?we1:we2;
        for (int kc = 0; kc < 4; ++kc) {
            __syncthreads();
            stage_panel(A2, (const float4*)(g_e + (size_t)m*H_ + kc*64), r, q);
            stage_panel(B2, (const float4*)(we + (size_t)(col0 + r)*H_ + kc*64), r, q);
            __syncthreads();
            accum64(A2, B2, tx, ty, acc);
        }
    }
    const float* bias = (mat==0)?bi:(mat==1)?bf:(mat==2)?bo:bg;
    float* dst = (mat==0)?g_pre_i:(mat==1)?g_pre_f:(mat==2)?g_pre_o:g_pre_g;
    float4 bv4 = *(const float4*)&bias[col0 + tx*4];
#pragma unroll
    for (int i = 0; i < 4; ++i) {
        size_t off = (size_t)(m0 + ty*4 + i)*H_ + col0 + tx*4;
        float4 v = make_float4(red2(acc[i][0])+bv4.x, red2(acc[i][1])+bv4.y,
                               red2(acc[i][2])+bv4.z, red2(acc[i][3])+bv4.w);
        *(float4*)&dst[off] = v;
    }
}

// ====== Kernel HO: pre_ho = xd@w_d^T + xw@w_w^T + xm@w_m^T + b_e ============
__global__ void k_ho(const float* __restrict__ x,
                     const float* __restrict__ w_d, const float* __restrict__ w_w,
                     const float* __restrict__ w_m, const float* __restrict__ b_e)
{
    __shared__ float2 A2[32*66];
    __shared__ float2 B2[32*66];
    int m0 = blockIdx.x * 64;
    int col0 = blockIdx.y * 64;
    int tid = threadIdx.x;
    int r = tid >> 2, q = tid & 3;
    int tx = tid & 15, ty = tid >> 4;
    int m = m0 + r;
    int b = m & (B_-1), t = m >> 7;

    u64 acc[4][4] = {};
    const int shifts[3] = {1, 7, 30};
#pragma unroll
    for (int s = 0; s < 3; ++s) {
        const float* ws = (s==0)?w_d:(s==1)?w_w:w_m;
        int bs = b - shifts[s];
        __syncthreads();
        if (bs >= 0) {
            stage_panel(A2, (const float4*)(x + ((size_t)bs*T_ + t)*I_), r, q);
        } else {
#pragma unroll
            for (int u = 0; u < 4; ++u) {
                int k2 = 2*(q + 4*u);
                A2[k2*66 + r]     = make_float2(0.f, 0.f);
                A2[(k2+1)*66 + r] = make_float2(0.f, 0.f);
            }
        }
        stage_panel(B2, (const float4*)(ws + (size_t)(col0 + r)*I_), r, q);
        __syncthreads();
        accum64(A2, B2, tx, ty, acc);
    }
    float4 bv4 = *(const float4*)&b_e[col0 + tx*4];
#pragma unroll
    for (int i = 0; i < 4; ++i) {
        size_t off = (size_t)(m0 + ty*4 + i)*H_ + col0 + tx*4;
        float4 v = make_float4(red2(acc[i][0])+bv4.x, red2(acc[i][1])+bv4.y,
                               red2(acc[i][2])+bv4.z, red2(acc[i][3])+bv4.w);
        *(float4*)&g_pre_ho[off] = v;
    }
}

// ======================= Recurrence (clustered persistent) ==================
// 16 clusters x 8 CTAs, 512 thr/CTA. Cluster g = batch rows [8g, 8g+8).
// CTA rank j owns H-cols [32j, 32j+32). No barrier.cluster in the loop:
// h exchange via packed st.async.b64 (even lanes ship col pairs), completion
// tracked by two local mbarriers (expect_tx = 8192 B per phase).
#define REC_SLICE_F (32*260)
#define REC_WT_OFF  0
#define REC_WI_OFF  (REC_SLICE_F)
#define REC_WG_OFF  (REC_SLICE_F*2)
#define REC_WF_OFF  (REC_SLICE_F*3)
#define REC_WO_OFF  (REC_SLICE_F*4)
#define REC_HB_F    (8*260)
#define REC_HN_OFF  (REC_SLICE_F*5)
#define REC_HO_OFF  (REC_HN_OFF + REC_HB_F)
#define REC_PP_OFF  (REC_HO_OFF + REC_HB_F)
#define REC_PP_F    8192
#define REC_MB_OFF  (REC_PP_OFF + REC_PP_F)         // 2 mbarriers, 16 B
#define REC_SMEM_FLOATS (REC_MB_OFF + 4)
#define REC_SMEM_BYTES  (REC_SMEM_FLOATS*4)
#define HB_BYTES    (REC_HB_F*4)
#define PHASE_TX    8192u

__global__ void __cluster_dims__(8,1,1) __launch_bounds__(512,1)
k_rec(const float* __restrict__ w_t, const float* __restrict__ w_ih,
      const float* __restrict__ w_gh, const float* __restrict__ w_fo,
      const float* __restrict__ w_oh, float* __restrict__ out)
{
    extern __shared__ float sm[];
    float*  wt_s = sm + REC_WT_OFF;
    float*  wi_s = sm + REC_WI_OFF;
    float*  wg_s = sm + REC_WG_OFF;
    float*  wf_s = sm + REC_WF_OFF;
    float*  wo_s = sm + REC_WO_OFF;
    float*  hn_s = sm + REC_HN_OFF;
    float*  ho_s = sm + REC_HO_OFF;
    float*  pp1   = sm + REC_PP_OFF;                 // phase1: [8r][16q][32c]
    float2* pp_ig = (float2*)(sm + REC_PP_OFF);      // phase2: [8r][8q][32c]
    float2* pp_fo = (float2*)(sm + REC_PP_OFF + 4096);

    int tid = threadIdx.x;
    int lane = tid & 31, warp = tid >> 5;
    int j = blockIdx.x & 7;        // cluster rank = H-slice
    int g = blockIdx.x >> 3;       // cluster id = batch group

    uint32_t mb_hn = smem_u32(&sm[REC_MB_OFF]);      // phase-2 output barrier
    uint32_t mb_ho = mb_hn + 8;                      // phase-1 output barrier

    // ---- load weight slices: wt + 4 gates, each [col][k] ----
    for (int idx = tid; idx < 32*64; idx += 512) {
        int col = idx >> 6, kq = idx & 63;
        *(float4*)&wt_s[col*260 + kq*4] =
            *(const float4*)(w_t + (size_t)(j*32+col)*H_ + kq*4);
    }
    for (int idx = tid; idx < 4*32*64; idx += 512) {
        int gg = idx >> 11, col = (idx >> 6) & 31, kq = idx & 63;
        const float* W = (gg==0)?w_ih:(gg==1)?w_gh:(gg==2)?w_fo:w_oh;
        float* S = (gg==0)?wi_s:(gg==1)?wg_s:(gg==2)?wf_s:wo_s;
        *(float4*)&S[col*260 + kq*4] =
            *(const float4*)(W + (size_t)(j*32+col)*H_ + kq*4);
    }
    for (int idx = tid; idx < REC_HB_F; idx += 512) hn_s[idx] = 0.f;
    if (tid == 0) {
        mb_init(mb_hn, 1);
        mb_init(mb_ho, 1);
        mb_expect_tx(mb_hn, PHASE_TX);   // pre-arm for step-0 writes
        mb_expect_tx(mb_ho, PHASE_TX);
    }
    __syncthreads();
    CLUSTER_SYNC();                      // mbarriers visible before any st.async

    int colA = lane;
    int q8 = warp & 7, gp = warp >> 3;   // phase-2 roles
    int k1 = warp * 16;                  // phase-1 k-range base (16 wide)
    int k2b = q8 * 32;                   // phase-2 k-range base (32 wide)
    const float* wA_s = gp ? wf_s : wi_s;
    const float* wB_s = gp ? wo_s : wg_s;
    float2* ppX = gp ? pp_fo : pp_ig;

    // finalize role: first 8 warps, one (row, col) output each
    bool fin = (tid < 256);
    bool sender = fin && ((lane & 1) == 0);   // even lanes ship col pairs
    int rowR = tid >> 5, colR = lane;    // valid when fin
    int cg   = j*32 + colR;
    int brow = g*8 + rowR;
    float c_state = 0.f;

    // loop-invariant remote addresses (data + mbarrier) per peer CTA.
    // Even lanes' own (row, col) address is the 8B-aligned pair base.
    uint32_t hn_rem[8], ho_rem[8], mbhn_rem[8], mbho_rem[8];
    if (sender) {
        uint32_t hn_local = smem_u32(&hn_s[rowR*260 + cg]);
#pragma unroll
        for (int p = 0; p < 8; ++p) {
            uint32_t ra, rm;
            asm("mapa.shared::cluster.u32 %0, %1, %2;"
                : "=r"(ra) : "r"(hn_local), "r"(p));
            asm("mapa.shared::cluster.u32 %0, %1, %2;"
                : "=r"(rm) : "r"(mb_hn), "r"(p));
            hn_rem[p] = ra;            ho_rem[p]   = ra + HB_BYTES;
            mbhn_rem[p] = rm;          mbho_rem[p] = rm + 8;
        }
    }

    // preload pre-activations for t=0
    float pho=0, pi=0, pg=0, pf=0, po=0;
    if (fin) {
        size_t pb = (size_t)brow*H_ + cg;
        pho = g_pre_ho[pb]; pi = g_pre_i[pb]; pg = g_pre_g[pb];
        pf  = g_pre_f [pb]; po = g_pre_o[pb];
    }

    for (int t = 0; t < T_; ++t) {
        uint32_t par = (uint32_t)(t & 1);
        // ---- phase 1: partial h_o = h_{t-1} @ w_t^T over 16-wide k-range ----
        u64 A1[8] = {};
#pragma unroll
        for (int kb = 0; kb < 16; kb += 4) {
            int k = k1 + kb;
            ulonglong2 wv = *(const ulonglong2*)&wt_s[colA*260 + k];
            ulonglong2 hv[8];
#pragma unroll
            for (int r = 0; r < 8; ++r)
                hv[r] = *(const ulonglong2*)&hn_s[r*260 + k];
#pragma unroll
            for (int r = 0; r < 8; ++r) {
                A1[r] = fma2(wv.x, hv[r].x, A1[r]);
                A1[r] = fma2(wv.y, hv[r].y, A1[r]);
            }
        }
#pragma unroll
        for (int r = 0; r < 8; ++r) pp1[(r*16 + warp)*32 + colA] = red2(A1[r]);
        __syncthreads();
        if (fin) {
            float s1 = pho;
#pragma unroll
            for (int qq = 0; qq < 16; ++qq) s1 += pp1[(rowR*16 + qq)*32 + colR];
            float hov = sigm(s1);
            float hop = __shfl_xor_sync(0xffffffffu, hov, 1);  // partner col
            if ((lane & 1) == 0) {
                u64 pk;
                asm("mov.b64 %0, {%1, %2};" : "=l"(pk) : "f"(hov), "f"(hop));
#pragma unroll
                for (int p = 0; p < 8; ++p)
                    st_async_b64(ho_rem[p], pk, mbho_rem[p]);
            }
        }
        // prefetch next step's pre-activations while DSMEM traffic drains
        float npho=pho, npi=pi, npg=pg, npf=pf, npo=po;
        if (fin) {
            int tn = (t+1 < T_) ? t+1 : t;
            size_t pb = ((size_t)tn*B_ + brow)*H_ + cg;
            npho = g_pre_ho[pb]; npi = g_pre_i[pb]; npg = g_pre_g[pb];
            npf  = g_pre_f [pb]; npo = g_pre_o[pb];
        }
        mb_wait(mb_ho, par);
        if (tid == 0) mb_expect_tx(mb_ho, PHASE_TX);   // re-arm for step t+1

        // ---- phase 2: partial gate pair = h_o @ W^T over 32-wide k-range ----
        u64 Aa[8] = {}, Ab[8] = {};
#pragma unroll
        for (int kb = 0; kb < 32; kb += 4) {
            int k = k2b + kb;
            ulonglong2 hv[8];
#pragma unroll
            for (int r = 0; r < 8; ++r)
                hv[r] = *(const ulonglong2*)&ho_s[r*260 + k];
            ulonglong2 wa = *(const ulonglong2*)&wA_s[colA*260 + k];
            ulonglong2 wb = *(const ulonglong2*)&wB_s[colA*260 + k];
#pragma unroll
            for (int r = 0; r < 8; ++r) {
                Aa[r] = fma2(wa.x, hv[r].x, Aa[r]);
                Aa[r] = fma2(wa.y, hv[r].y, Aa[r]);
                Ab[r] = fma2(wb.x, hv[r].x, Ab[r]);
                Ab[r] = fma2(wb.y, hv[r].y, Ab[r]);
            }
        }
#pragma unroll
        for (int r = 0; r < 8; ++r)
            ppX[(r*8 + q8)*32 + colA] = make_float2(red2(Aa[r]), red2(Ab[r]));
        __syncthreads();
        if (fin) {
            float si = pi, sg = pg, sf = pf, so = po;
#pragma unroll
            for (int qq = 0; qq < 8; ++qq) {
                float2 vig = pp_ig[(rowR*8 + qq)*32 + colR];
                float2 vfo = pp_fo[(rowR*8 + qq)*32 + colR];
                si += vig.x; sg += vig.y; sf += vfo.x; so += vfo.y;
            }
            float iv = sigm(si), gv = tanh_f(sg), fv = sigm(sf), ov = sigm(so);
            c_state = fv*c_state + iv*gv;
            float hnv = ov * tanh_f(c_state);
            float hnp = __shfl_xor_sync(0xffffffffu, hnv, 1);  // partner col
            if ((lane & 1) == 0) {
                u64 pk;
                asm("mov.b64 %0, {%1, %2};" : "=l"(pk) : "f"(hnv), "f"(hnp));
#pragma unroll
                for (int p = 0; p < 8; ++p)
                    st_async_b64(hn_rem[p], pk, mbhn_rem[p]);
            }
            // output stores overlap with DSMEM drain
            size_t obase = ((size_t)brow*T_ + t)*H_ + cg;
            out[obase] = hnv;
            out[(size_t)BT_*H_ + obase] = c_state;
            pho = npho; pi = npi; pg = npg; pf = npf; po = npo;
        }
        mb_wait(mb_hn, par);
        if (tid == 0) mb_expect_tx(mb_hn, PHASE_TX);   // re-arm for step t+1
    }
}

// ============================== launch ======================================
extern "C" void kernel_launch(void* const* d_in, const int* in_sizes, int n_in,
                              void* d_out, int out_size)
{
    const float* x    = (const float*)d_in[0];
    const float* xw   = (const float*)d_in[1];
    const float* w_ix = (const float*)d_in[2];
    const float* w_ih = (const float*)d_in[3];
    const float* w_ie = (const float*)d_in[4];
    const float* b_i  = (const float*)d_in[5];
    const float* w_fx = (const float*)d_in[6];
    const float* w_fo = (const float*)d_in[7];
    const float* w_fe = (const float*)d_in[8];
    const float* b_f  = (const float*)d_in[9];
    const float* w_ox = (const float*)d_in[10];
    const float* w_oh = (const float*)d_in[11];
    const float* w_oe = (const float*)d_in[12];
    const float* b_o  = (const float*)d_in[13];
    const float* w_gx = (const float*)d_in[14];
    const float* w_gh = (const float*)d_in[15];
    const float* b_g  = (const float*)d_in[16];
    const float* w_d  = (const float*)d_in[17];
    const float* w_w  = (const float*)d_in[18];
    const float* w_m  = (const float*)d_in[19];
    const float* w_t  = (const float*)d_in[20];
    const float* w_e  = (const float*)d_in[21];
    const float* b_e  = (const float*)d_in[22];
    float* out = (float*)d_out;

    k_e <<<BT_/8, 256>>>(xw, w_e, b_e);
    k_ho<<<dim3(BT_/64, 4), 256>>>(x, w_d, w_w, w_m, b_e);
    k_xe<<<dim3(BT_/64, 16), 256>>>(x, w_ix, w_fx, w_ox, w_gx,
                                    w_ie, w_fe, w_oe, b_i, b_f, b_o, b_g);

    static int smem_set = 0;
    if (!smem_set) {
        cudaFuncSetAttribute(k_rec, cudaFuncAttributeMaxDynamicSharedMemorySize,
                             REC_SMEM_BYTES);
        smem_set = 1;
    }
    k_rec<<<128, 512, REC_SMEM_BYTES>>>(w_t, w_ih, w_gh, w_fo, w_oh, out);
}

// round 13
// speedup vs baseline: 1.1244x; 1.1244x over previous
#include <cuda_runtime.h>
#include <cuda_bf16.h>
#include <stdint.h>

#define B_ 128
#define T_ 1024
#define I_ 64
#define W_ 32
#define H_ 256
#define BT_ (B_*T_)

typedef unsigned long long u64;

// ---------------- scratch (__device__ globals are allowed) ------------------
__device__ float g_e     [(size_t)BT_*H_];   // [T][B][H]
__device__ float g_pre_ho[(size_t)BT_*H_];   // [T][B][H]
__device__ float g_pre_i [(size_t)BT_*H_];
__device__ float g_pre_g [(size_t)BT_*H_];
__device__ float g_pre_f [(size_t)BT_*H_];
__device__ float g_pre_o [(size_t)BT_*H_];

__device__ __forceinline__ float sigm(float x) { return 1.f / (1.f + __expf(-x)); }
__device__ __forceinline__ float tanh_f(float x) {
    float e = __expf(2.f * x);
    return 1.f - __fdividef(2.f, e + 1.f);
}

// packed f32x2 FMA (sm_100+)
__device__ __forceinline__ u64 fma2(u64 a, u64 b, u64 c) {
    u64 d;
    asm("fma.rn.f32x2 %0, %1, %2, %3;" : "=l"(d) : "l"(a), "l"(b), "l"(c));
    return d;
}
__device__ __forceinline__ float red2(u64 v) {
    float x, y;
    asm("mov.b64 {%0, %1}, %2;" : "=f"(x), "=f"(y) : "l"(v));
    return x + y;
}

__device__ __forceinline__ uint32_t smem_u32(const void* p) {
    uint32_t a;
    asm("{ .reg .u64 t; cvta.to.shared.u64 t, %1; cvt.u32.u64 %0, t; }" : "=r"(a) : "l"(p));
    return a;
}
#define CLUSTER_SYNC() do { \
    asm volatile("barrier.cluster.arrive.aligned;" ::: "memory"); \
    asm volatile("barrier.cluster.wait.aligned;"   ::: "memory"); \
} while (0)

// remote DSMEM store fused with tx-signal on dest CTA's mbarrier
__device__ __forceinline__ void st_async_f32(uint32_t raddr, float v, uint32_t rmbar) {
    asm volatile(
        "st.async.shared::cluster.mbarrier::complete_tx::bytes.f32 [%0], %1, [%2];"
        :: "r"(raddr), "f"(v), "r"(rmbar) : "memory");
}
__device__ __forceinline__ void mb_init(uint32_t mbar, uint32_t cnt) {
    asm volatile("mbarrier.init.shared.b64 [%0], %1;" :: "r"(mbar), "r"(cnt) : "memory");
}
__device__ __forceinline__ void mb_expect_tx(uint32_t mbar, uint32_t bytes) {
    asm volatile("mbarrier.arrive.expect_tx.shared.b64 _, [%0], %1;"
                 :: "r"(mbar), "r"(bytes) : "memory");
}
__device__ __forceinline__ void mb_wait(uint32_t mbar, uint32_t parity) {
    uint32_t done;
    asm volatile(
        "{\n\t.reg .pred p;\n\t"
        "mbarrier.try_wait.parity.acquire.cluster.shared::cta.b64 p, [%1], %2;\n\t"
        "selp.b32 %0, 1, 0, p;\n\t}"
        : "=r"(done) : "r"(mbar), "r"(parity) : "memory");
    if (!done) {
        asm volatile(
            "{\n\t.reg .pred P1;\n\t"
            "WL_%=:\n\t"
            "mbarrier.try_wait.parity.acquire.cluster.shared::cta.b64 P1, [%0], %1, 0x989680;\n\t"
            "@P1 bra.uni WD_%=;\n\t"
            "bra.uni WL_%=;\n\t"
            "WD_%=:\n\t}"
            :: "r"(mbar), "r"(parity) : "memory");
    }
}

// ========================== Kernel E: e = sigmoid(xw @ w_e^T + b_e) =========
__global__ void k_e(const float* __restrict__ xw, const float* __restrict__ w_e,
                    const float* __restrict__ b_e)
{
    __shared__ float sx[8][32];
    int h = threadIdx.x;
    int bt0 = blockIdx.x * 8;
    {
        int p = h >> 5, k = h & 31;
        int bt = bt0 + p;
        int b = bt >> 10, t = bt & 1023;
        sx[p][k] = xw[((size_t)b*T_ + t)*W_ + k];
    }
    __syncthreads();
    float4 wr[8];
    const float4* wp = (const float4*)(w_e + (size_t)h*W_);
#pragma unroll
    for (int u = 0; u < 8; ++u) wr[u] = wp[u];
    float bias = b_e[h];
#pragma unroll
    for (int p = 0; p < 8; ++p) {
        float acc = bias;
#pragma unroll
        for (int u = 0; u < 8; ++u) {
            acc += wr[u].x*sx[p][4*u+0] + wr[u].y*sx[p][4*u+1]
                 + wr[u].z*sx[p][4*u+2] + wr[u].w*sx[p][4*u+3];
        }
        int bt = bt0 + p;
        int b = bt >> 10, t = bt & 1023;
        g_e[((size_t)t*B_ + b)*H_ + h] = sigm(acc);
    }
}

// ------- shared helpers for 64x64 fp32x2 tiles (k-pair float2 layout) -------
__device__ __forceinline__ void stage_panel(float2* S, const float4* src,
                                            int r, int q)
{
#pragma unroll
    for (int u = 0; u < 4; ++u) {
        float4 v = src[q + 4*u];
        int k2 = 2*(q + 4*u);
        S[k2*66 + r]       = make_float2(v.x, v.y);
        S[(k2+1)*66 + r]   = make_float2(v.z, v.w);
    }
}
__device__ __forceinline__ void accum64(const float2* A2, const float2* B2,
                                        int tx, int ty, u64 acc[4][4])
{
#pragma unroll 8
    for (int k2 = 0; k2 < 32; ++k2) {
        ulonglong2 aL = *(const ulonglong2*)(A2 + k2*66 + ty*4);
        ulonglong2 aH = *(const ulonglong2*)(A2 + k2*66 + ty*4 + 2);
        ulonglong2 bL = *(const ulonglong2*)(B2 + k2*66 + tx*4);
        ulonglong2 bH = *(const ulonglong2*)(B2 + k2*66 + tx*4 + 2);
        u64 av[4] = {aL.x, aL.y, aH.x, aH.y};
        u64 bv[4] = {bL.x, bL.y, bH.x, bH.y};
#pragma unroll
        for (int i = 0; i < 4; ++i)
#pragma unroll
            for (int j = 0; j < 4; ++j) acc[i][j] = fma2(av[i], bv[j], acc[i][j]);
    }
}

// ===== Kernel XE: pre_X = x@w_Xx^T (+ e@w_Xe^T for i,f,o) + b_X  ============
__global__ void k_xe(const float* __restrict__ x,
                     const float* __restrict__ wx0, const float* __restrict__ wx1,
                     const float* __restrict__ wx2, const float* __restrict__ wx3,
                     const float* __restrict__ we0, const float* __restrict__ we1,
                     const float* __restrict__ we2,
                     const float* __restrict__ bi, const float* __restrict__ bf,
                     const float* __restrict__ bo, const float* __restrict__ bg)
{
    __shared__ float2 A2[32*66];
    __shared__ float2 B2[32*66];
    int m0 = blockIdx.x * 64;
    int gy = blockIdx.y;
    int mat = gy >> 2;
    int col0 = (gy & 3) * 64;
    const float* wx = (mat==0)?wx0:(mat==1)?wx1:(mat==2)?wx2:wx3;
    int tid = threadIdx.x;
    int r = tid >> 2, q = tid & 3;
    int tx = tid & 15, ty = tid >> 4;
    int m = m0 + r;
    int b = m & (B_-1), t = m >> 7;

    u64 acc[4][4] = {};
    stage_panel(A2, (const float4*)(x + ((size_t)b*T_ + t)*I_), r, q);
    stage_panel(B2, (const float4*)(wx + (size_t)(col0 + r)*I_), r, q);
    __syncthreads();
    accum64(A2, B2, tx, ty, acc);
    if (mat < 3) {
        const float* we = (mat==0)?we0:(mat==1)?we1:we2;
        for (int kc = 0; kc < 4; ++kc) {
            __syncthreads();
            stage_panel(A2, (const float4*)(g_e + (size_t)m*H_ + kc*64), r, q);
            stage_panel(B2, (const float4*)(we + (size_t)(col0 + r)*H_ + kc*64), r, q);
            __syncthreads();
            accum64(A2, B2, tx, ty, acc);
        }
    }
    const float* bias = (mat==0)?bi:(mat==1)?bf:(mat==2)?bo:bg;
    float* dst = (mat==0)?g_pre_i:(mat==1)?g_pre_f:(mat==2)?g_pre_o:g_pre_g;
    float4 bv4 = *(const float4*)&bias[col0 + tx*4];
#pragma unroll
    for (int i = 0; i < 4; ++i) {
        size_t off = (size_t)(m0 + ty*4 + i)*H_ + col0 + tx*4;
        float4 v = make_float4(red2(acc[i][0])+bv4.x, red2(acc[i][1])+bv4.y,
                               red2(acc[i][2])+bv4.z, red2(acc[i][3])+bv4.w);
        *(float4*)&dst[off] = v;
    }
}

// ====== Kernel HO: pre_ho = xd@w_d^T + xw@w_w^T + xm@w_m^T + b_e ============
__global__ void k_ho(const float* __restrict__ x,
                     const float* __restrict__ w_d, const float* __restrict__ w_w,
                     const float* __restrict__ w_m, const float* __restrict__ b_e)
{
    __shared__ float2 A2[32*66];
    __shared__ float2 B2[32*66];
    int m0 = blockIdx.x * 64;
    int col0 = blockIdx.y * 64;
    int tid = threadIdx.x;
    int r = tid >> 2, q = tid & 3;
    int tx = tid & 15, ty = tid >> 4;
    int m = m0 + r;
    int b = m & (B_-1), t = m >> 7;

    u64 acc[4][4] = {};
    const int shifts[3] = {1, 7, 30};
#pragma unroll
    for (int s = 0; s < 3; ++s) {
        const float* ws = (s==0)?w_d:(s==1)?w_w:w_m;
        int bs = b - shifts[s];
        __syncthreads();
        if (bs >= 0) {
            stage_panel(A2, (const float4*)(x + ((size_t)bs*T_ + t)*I_), r, q);
        } else {
#pragma unroll
            for (int u = 0; u < 4; ++u) {
                int k2 = 2*(q + 4*u);
                A2[k2*66 + r]     = make_float2(0.f, 0.f);
                A2[(k2+1)*66 + r] = make_float2(0.f, 0.f);
            }
        }
        stage_panel(B2, (const float4*)(ws + (size_t)(col0 + r)*I_), r, q);
        __syncthreads();
        accum64(A2, B2, tx, ty, acc);
    }
    float4 bv4 = *(const float4*)&b_e[col0 + tx*4];
#pragma unroll
    for (int i = 0; i < 4; ++i) {
        size_t off = (size_t)(m0 + ty*4 + i)*H_ + col0 + tx*4;
        float4 v = make_float4(red2(acc[i][0])+bv4.x, red2(acc[i][1])+bv4.y,
                               red2(acc[i][2])+bv4.z, red2(acc[i][3])+bv4.w);
        *(float4*)&g_pre_ho[off] = v;
    }
}

// ======================= Recurrence (dual-group pipelined cluster) ==========
// 8 clusters x 8 CTAs, 512 thr/CTA. Cluster g owns batch rows [16g, 16g+16):
// group A = rows [16g,16g+8), group B = rows [16g+8,16g+16).
// CTA rank j owns H-cols [32j, 32j+32); weight slices shared by both groups.
// Per step: P1A -> P1B -> P2A -> P2B; every mbarrier wait is covered by the
// other group's compute phase. 4 mbarriers (hnA,hoA,hnB,hoB), tx=8192 B each.
#define RW_F     8320            // weight slice floats (32 cols x 260)
#define RH_F     2048            // h buffer floats (8 rows x 256; bcast reads)
#define OFF_WT   0
#define OFF_WI   8320
#define OFF_WG   16640
#define OFF_WF   24960
#define OFF_WO   33280
#define OFF_HNA  41600
#define OFF_HOA  43648
#define OFF_HNB  45696
#define OFF_HOB  47744
#define OFF_PP   49792           // 8192 floats (shared by all phases)
#define OFF_MB   57984           // 4 mbarriers = 32 B
#define REC_SMEM_FLOATS 57992
#define REC_SMEM_BYTES  (REC_SMEM_FLOATS*4)
#define D_HOA    8192            // byte deltas from an hnA element
#define D_HNB    16384
#define D_HOB    24576
#define PHASE_TX 8192u

__device__ __forceinline__ void rec_phase1(const float* wt_s, const float* hn,
                                           float* pp1, int warp, int colA, int k1)
{
    u64 A1[8] = {};
#pragma unroll
    for (int kb = 0; kb < 16; kb += 4) {
        int k = k1 + kb;
        ulonglong2 wv = *(const ulonglong2*)&wt_s[colA*260 + k];
        ulonglong2 hv[8];
#pragma unroll
        for (int r = 0; r < 8; ++r) hv[r] = *(const ulonglong2*)&hn[r*256 + k];
#pragma unroll
        for (int r = 0; r < 8; ++r) {
            A1[r] = fma2(wv.x, hv[r].x, A1[r]);
            A1[r] = fma2(wv.y, hv[r].y, A1[r]);
        }
    }
#pragma unroll
    for (int r = 0; r < 8; ++r) pp1[(r*16 + warp)*32 + colA] = red2(A1[r]);
}

__device__ __forceinline__ void rec_phase2(const float* wA_s, const float* wB_s,
                                           const float* ho, float2* ppX,
                                           int q8, int colA, int k2b)
{
    u64 Aa[8] = {}, Ab[8] = {};
#pragma unroll
    for (int kb = 0; kb < 32; kb += 4) {
        int k = k2b + kb;
        ulonglong2 hv[8];
#pragma unroll
        for (int r = 0; r < 8; ++r) hv[r] = *(const ulonglong2*)&ho[r*256 + k];
        ulonglong2 wa = *(const ulonglong2*)&wA_s[colA*260 + k];
        ulonglong2 wb = *(const ulonglong2*)&wB_s[colA*260 + k];
#pragma unroll
        for (int r = 0; r < 8; ++r) {
            Aa[r] = fma2(wa.x, hv[r].x, Aa[r]);
            Aa[r] = fma2(wa.y, hv[r].y, Aa[r]);
            Ab[r] = fma2(wb.x, hv[r].x, Ab[r]);
            Ab[r] = fma2(wb.y, hv[r].y, Ab[r]);
        }
    }
#pragma unroll
    for (int r = 0; r < 8; ++r)
        ppX[(r*8 + q8)*32 + colA] = make_float2(red2(Aa[r]), red2(Ab[r]));
}

__global__ void __cluster_dims__(8,1,1) __launch_bounds__(512,1)
k_rec(const float* __restrict__ w_t, const float* __restrict__ w_ih,
      const float* __restrict__ w_gh, const float* __restrict__ w_fo,
      const float* __restrict__ w_oh, float* __restrict__ out)
{
    extern __shared__ float sm[];
    float*  wt_s  = sm + OFF_WT;
    float*  wi_s  = sm + OFF_WI;
    float*  wg_s  = sm + OFF_WG;
    float*  wf_s  = sm + OFF_WF;
    float*  wo_s  = sm + OFF_WO;
    float*  hnA_s = sm + OFF_HNA;
    float*  hoA_s = sm + OFF_HOA;
    float*  hnB_s = sm + OFF_HNB;
    float*  hoB_s = sm + OFF_HOB;
    float*  pp1   = sm + OFF_PP;                     // phase1: [8r][16q][32c]
    float2* pp_ig = (float2*)(sm + OFF_PP);          // phase2: [8r][8q][32c]
    float2* pp_fo = (float2*)(sm + OFF_PP + 4096);

    int tid = threadIdx.x;
    int lane = tid & 31, warp = tid >> 5;
    int j = blockIdx.x & 7;        // cluster rank = H-slice
    int g = blockIdx.x >> 3;       // cluster id = batch group pair

    uint32_t mbL = smem_u32(&sm[OFF_MB]);
    uint32_t mbL_hnA = mbL, mbL_hoA = mbL + 8, mbL_hnB = mbL + 16, mbL_hoB = mbL + 24;

    // ---- load weight slices: wt + 4 gates, each [col][k] ----
    for (int idx = tid; idx < 32*64; idx += 512) {
        int col = idx >> 6, kq = idx & 63;
        *(float4*)&wt_s[col*260 + kq*4] =
            *(const float4*)(w_t + (size_t)(j*32+col)*H_ + kq*4);
    }
    for (int idx = tid; idx < 4*32*64; idx += 512) {
        int gg = idx >> 11, col = (idx >> 6) & 31, kq = idx & 63;
        const float* W = (gg==0)?w_ih:(gg==1)?w_gh:(gg==2)?w_fo:w_oh;
        float* S = (gg==0)?wi_s:(gg==1)?wg_s:(gg==2)?wf_s:wo_s;
        *(float4*)&S[col*260 + kq*4] =
            *(const float4*)(W + (size_t)(j*32+col)*H_ + kq*4);
    }
    for (int idx = tid; idx < 4*RH_F; idx += 512) hnA_s[idx] = 0.f;  // hnA..hoB
    if (tid == 0) {
        mb_init(mbL_hnA, 1); mb_init(mbL_hoA, 1);
        mb_init(mbL_hnB, 1); mb_init(mbL_hoB, 1);
        mb_expect_tx(mbL_hnA, PHASE_TX);
        mb_expect_tx(mbL_hoA, PHASE_TX);
        mb_expect_tx(mbL_hnB, PHASE_TX);
        mb_expect_tx(mbL_hoB, PHASE_TX);
    }
    __syncthreads();
    CLUSTER_SYNC();                      // mbarriers visible before any st.async

    int colA = lane;
    int q8 = warp & 7, gp = warp >> 3;   // phase-2 roles
    int k1 = warp * 16;                  // phase-1 k-range base (16 wide)
    int k2b = q8 * 32;                   // phase-2 k-range base (32 wide)
    const float* wA_s = gp ? wf_s : wi_s;
    const float* wB_s = gp ? wo_s : wg_s;
    float2* ppX = gp ? pp_fo : pp_ig;

    bool fin = (tid < 256);
    int rowR = tid >> 5, colR = lane;    // valid when fin
    int cg    = j*32 + colR;
    int browA = g*16 + rowR;
    int browB = browA + 8;
    float cA = 0.f, cB = 0.f;

    // loop-invariant remote addresses per peer CTA
    uint32_t hnA_rem[8], mb_rem[8];
    if (fin) {
        uint32_t hnA_loc = smem_u32(&hnA_s[rowR*256 + cg]);
#pragma unroll
        for (int p = 0; p < 8; ++p) {
            asm("mapa.shared::cluster.u32 %0, %1, %2;"
                : "=r"(hnA_rem[p]) : "r"(hnA_loc), "r"(p));
            asm("mapa.shared::cluster.u32 %0, %1, %2;"
                : "=r"(mb_rem[p]) : "r"(mbL), "r"(p));
        }
        // pre-flip mb_hnB with a real send of the initial zeros (parity stays t&1)
#pragma unroll
        for (int p = 0; p < 8; ++p)
            st_async_f32(hnA_rem[p] + D_HNB, 0.f, mb_rem[p] + 16);
    }

    // preload pre-activations for t=0 (both groups)
    float phoA=0, piA=0, pgA=0, pfA=0, poA=0;
    float phoB=0, piB=0, pgB=0, pfB=0, poB=0;
    if (fin) {
        size_t pa = (size_t)browA*H_ + cg;
        size_t pb = (size_t)browB*H_ + cg;
        phoA=g_pre_ho[pa]; piA=g_pre_i[pa]; pgA=g_pre_g[pa]; pfA=g_pre_f[pa]; poA=g_pre_o[pa];
        phoB=g_pre_ho[pb]; piB=g_pre_i[pb]; pgB=g_pre_g[pb]; pfB=g_pre_f[pb]; poB=g_pre_o[pb];
    }

    for (int t = 0; t < T_; ++t) {
        uint32_t par = (uint32_t)(t & 1);

        // ---- P1A ----
        rec_phase1(wt_s, hnA_s, pp1, warp, colA, k1);
        __syncthreads();
        if (fin) {
            float s1 = phoA;
#pragma unroll
            for (int qq = 0; qq < 16; ++qq) s1 += pp1[(rowR*16 + qq)*32 + colR];
            float hov = sigm(s1);
#pragma unroll
            for (int p = 0; p < 8; ++p)
                st_async_f32(hnA_rem[p] + D_HOA, hov, mb_rem[p] + 8);
        }
        __syncthreads();                       // pp reuse guard
        mb_wait(mbL_hnB, par);                 // hnB from step t-1 (covered by P1A)
        if (tid == 0) mb_expect_tx(mbL_hnB, PHASE_TX);

        // ---- P1B ----
        rec_phase1(wt_s, hnB_s, pp1, warp, colA, k1);
        __syncthreads();
        if (fin) {
            float s1 = phoB;
#pragma unroll
            for (int qq = 0; qq < 16; ++qq) s1 += pp1[(rowR*16 + qq)*32 + colR];
            float hov = sigm(s1);
#pragma unroll
            for (int p = 0; p < 8; ++p)
                st_async_f32(hnA_rem[p] + D_HOB, hov, mb_rem[p] + 24);
        }
        // prefetch next step's pre-activations (both groups)
        float nphoA=phoA, npiA=piA, npgA=pgA, npfA=pfA, npoA=poA;
        float nphoB=phoB, npiB=piB, npgB=pgB, npfB=pfB, npoB=poB;
        if (fin) {
            int tn = (t+1 < T_) ? t+1 : t;
            size_t pa = ((size_t)tn*B_ + browA)*H_ + cg;
            size_t pb = ((size_t)tn*B_ + browB)*H_ + cg;
            nphoA=g_pre_ho[pa]; npiA=g_pre_i[pa]; npgA=g_pre_g[pa]; npfA=g_pre_f[pa]; npoA=g_pre_o[pa];
            nphoB=g_pre_ho[pb]; npiB=g_pre_i[pb]; npgB=g_pre_g[pb]; npfB=g_pre_f[pb]; npoB=g_pre_o[pb];
        }
        __syncthreads();
        mb_wait(mbL_hoA, par);                 // hoA (covered by P1B)
        if (tid == 0) mb_expect_tx(mbL_hoA, PHASE_TX);

        // ---- P2A ----
        rec_phase2(wA_s, wB_s, hoA_s, ppX, q8, colA, k2b);
        __syncthreads();
        if (fin) {
            float si = piA, sg = pgA, sf = pfA, so = poA;
#pragma unroll
            for (int qq = 0; qq < 8; ++qq) {
                float2 vig = pp_ig[(rowR*8 + qq)*32 + colR];
                float2 vfo = pp_fo[(rowR*8 + qq)*32 + colR];
                si += vig.x; sg += vig.y; sf += vfo.x; so += vfo.y;
            }
            float iv = sigm(si), gv = tanh_f(sg), fv = sigm(sf), ov = sigm(so);
            cA = fv*cA + iv*gv;
            float hnv = ov * tanh_f(cA);
#pragma unroll
            for (int p = 0; p < 8; ++p)
                st_async_f32(hnA_rem[p], hnv, mb_rem[p]);
            size_t ob = ((size_t)browA*T_ + t)*H_ + cg;
            out[ob] = hnv;
            out[(size_t)BT_*H_ + ob] = cA;
        }
        __syncthreads();                       // pp reuse guard
        mb_wait(mbL_hoB, par);                 // hoB (covered by P2A)
        if (tid == 0) mb_expect_tx(mbL_hoB, PHASE_TX);

        // ---- P2B ----
        rec_phase2(wA_s, wB_s, hoB_s, ppX, q8, colA, k2b);
        __syncthreads();
        if (fin) {
            float si = piB, sg = pgB, sf = pfB, so = poB;
#pragma unroll
            for (int qq = 0; qq < 8; ++qq) {
                float2 vig = pp_ig[(rowR*8 + qq)*32 + colR];
                float2 vfo = pp_fo[(rowR*8 + qq)*32 + colR];
                si += vig.x; sg += vig.y; sf += vfo.x; so += vfo.y;
            }
            float iv = sigm(si), gv = tanh_f(sg), fv = sigm(sf), ov = sigm(so);
            cB = fv*cB + iv*gv;
            float hnv = ov * tanh_f(cB);
#pragma unroll
            for (int p = 0; p < 8; ++p)
                st_async_f32(hnA_rem[p] + D_HNB, hnv, mb_rem[p] + 16);
            size_t ob = ((size_t)browB*T_ + t)*H_ + cg;
            out[ob] = hnv;
            out[(size_t)BT_*H_ + ob] = cB;
            phoA=nphoA; piA=npiA; pgA=npgA; pfA=npfA; poA=npoA;
            phoB=nphoB; piB=npiB; pgB=npgB; pfB=npfB; poB=npoB;
        }
        __syncthreads();
        mb_wait(mbL_hnA, par);                 // hnA (covered by P2B)
        if (tid == 0) mb_expect_tx(mbL_hnA, PHASE_TX);
    }
    // drain the final hnB sends before exit (parity continues: t=1024 -> 0)
    mb_wait(mbL_hnB, 0);
    CLUSTER_SYNC();
}

// ============================== launch ======================================
extern "C" void kernel_launch(void* const* d_in, const int* in_sizes, int n_in,
                              void* d_out, int out_size)
{
    const float* x    = (const float*)d_in[0];
    const float* xw   = (const float*)d_in[1];
    const float* w_ix = (const float*)d_in[2];
    const float* w_ih = (const float*)d_in[3];
    const float* w_ie = (const float*)d_in[4];
    const float* b_i  = (const float*)d_in[5];
    const float* w_fx = (const float*)d_in[6];
    const float* w_fo = (const float*)d_in[7];
    const float* w_fe = (const float*)d_in[8];
    const float* b_f  = (const float*)d_in[9];
    const float* w_ox = (const float*)d_in[10];
    const float* w_oh = (const float*)d_in[11];
    const float* w_oe = (const float*)d_in[12];
    const float* b_o  = (const float*)d_in[13];
    const float* w_gx = (const float*)d_in[14];
    const float* w_gh = (const float*)d_in[15];
    const float* b_g  = (const float*)d_in[16];
    const float* w_d  = (const float*)d_in[17];
    const float* w_w  = (const float*)d_in[18];
    const float* w_m  = (const float*)d_in[19];
    const float* w_t  = (const float*)d_in[20];
    const float* w_e  = (const float*)d_in[21];
    const float* b_e  = (const float*)d_in[22];
    float* out = (float*)d_out;

    k_e <<<BT_/8, 256>>>(xw, w_e, b_e);
    k_ho<<<dim3(BT_/64, 4), 256>>>(x, w_d, w_w, w_m, b_e);
    k_xe<<<dim3(BT_/64, 16), 256>>>(x, w_ix, w_fx, w_ox, w_gx,
                                    w_ie, w_fe, w_oe, b_i, b_f, b_o, b_g);

    static int smem_set = 0;
    if (!smem_set) {
        cudaFuncSetAttribute(k_rec, cudaFuncAttributeMaxDynamicSharedMemorySize,
                             REC_SMEM_BYTES);
        smem_set = 1;
    }
    k_rec<<<64, 512, REC_SMEM_BYTES>>>(w_t, w_ih, w_gh, w_fo, w_oh, out);
}